// round 9
// baseline (speedup 1.0000x reference)
#include <cuda_runtime.h>
#include <cuda_bf16.h>
#include <cstdint>

#define Hd 512
#define Bd 128
#define Td 2048
#define Md (Bd * Td)
#define BM 128

#define TSTRIDE 144                     // 72 bf16 per padded tile row
#define TILE_BYTES (128 * TSTRIDE)      // 18432
// smem layout
#define SM_BS    0
#define SM_VA    2048
#define SM_RED   4096
#define SM_BUF0  4608
#define SM_BUF1  (SM_BUF0 + 4 * TILE_BYTES)   // 78336
#define OFF_XH   0
#define OFF_XL   TILE_BYTES
#define OFF_WH   (2 * TILE_BYTES)
#define OFF_WL   (3 * TILE_BYTES)
#define SMEM_TOTAL (SM_BUF1 + 4 * TILE_BYTES) // 152064

__device__ __nv_bfloat16 g_Whi[Hd * Hd];
__device__ __nv_bfloat16 g_Wlo[Hd * Hd];
__device__ __nv_bfloat16 g_xhi[Md * Hd];
__device__ __nv_bfloat16 g_xlo[Md * Hd];
__device__ float g_bsum[Hd];
__device__ float g_score[Md];

__device__ __forceinline__ uint32_t smem_to_u32(const void* p) {
    uint32_t a;
    asm("{ .reg .u64 t; cvta.to.shared.u64 t, %1; cvt.u32.u64 %0, t; }" : "=r"(a) : "l"(p));
    return a;
}
__device__ __forceinline__ void cpasync16(uint32_t s, const void* g) {
    asm volatile("cp.async.cg.shared.global [%0], [%1], 16;" :: "r"(s), "l"(g));
}
#define CP_COMMIT() asm volatile("cp.async.commit_group;" ::: "memory")
#define CP_WAIT(n)  asm volatile("cp.async.wait_group %0;" :: "n"(n) : "memory")

__device__ __forceinline__ void ldsm_x4(uint32_t& r0, uint32_t& r1, uint32_t& r2,
                                        uint32_t& r3, uint32_t addr) {
    asm volatile("ldmatrix.sync.aligned.m8n8.x4.shared.b16 {%0,%1,%2,%3}, [%4];"
                 : "=r"(r0), "=r"(r1), "=r"(r2), "=r"(r3) : "r"(addr));
}
__device__ __forceinline__ void mma16816(float* d, const uint32_t* a, const uint32_t* b) {
    asm volatile("mma.sync.aligned.m16n8k16.row.col.f32.bf16.bf16.f32 "
                 "{%0,%1,%2,%3}, {%4,%5,%6,%7}, {%8,%9}, {%0,%1,%2,%3};"
                 : "+f"(d[0]), "+f"(d[1]), "+f"(d[2]), "+f"(d[3])
                 : "r"(a[0]), "r"(a[1]), "r"(a[2]), "r"(a[3]), "r"(b[0]), "r"(b[1]));
}

// ---------------------------------------------------------------------------
// Kernel 1: Wsum -> bf16 hi/lo split; bsum.
// ---------------------------------------------------------------------------
__global__ void prep_kernel(const float* __restrict__ Wa_w, const float* __restrict__ Ua_w,
                            const float* __restrict__ Wa_b, const float* __restrict__ Ua_b) {
    int i = blockIdx.x * blockDim.x + threadIdx.x;
    if (i < Hd * Hd) {
        float w = Wa_w[i] + Ua_w[i];
        __nv_bfloat16 h = __float2bfloat16(w);
        g_Whi[i] = h;
        g_Wlo[i] = __float2bfloat16(w - __bfloat162float(h));
    }
    if (i < Hd) g_bsum[i] = Wa_b[i] + Ua_b[i];
}

// ---------------------------------------------------------------------------
// Kernel 2: score GEMM via mma.sync bf16 (hh+hl+lh), cp.async double-buffered.
// nb==0: converts x fp32 -> bf16 hi/lo (smem + global side-store).
// nb>=1: pure cp.async pipeline from pre-converted bf16.
// ---------------------------------------------------------------------------
__device__ __forceinline__ void load_w_async(char* smem, uint32_t bufoff, int nb, int kt,
                                             int tid) {
    const uint32_t sb = smem_to_u32(smem);
#pragma unroll
    for (int q = 0; q < 4; q++) {
        int idx = tid + q * 256;            // 0..1023
        int r = idx >> 3, c8 = idx & 7;
        uint32_t soff = (uint32_t)(r * TSTRIDE + c8 * 16);
        size_t g = (size_t)(nb * 128 + r) * Hd + kt * 64 + c8 * 8;
        cpasync16(sb + bufoff + OFF_WH + soff, &g_Whi[g]);
        cpasync16(sb + bufoff + OFF_WL + soff, &g_Wlo[g]);
    }
}
__device__ __forceinline__ void load_x_async(char* smem, uint32_t bufoff, int row0, int kt,
                                             int tid) {
    const uint32_t sb = smem_to_u32(smem);
#pragma unroll
    for (int q = 0; q < 4; q++) {
        int idx = tid + q * 256;
        int r = idx >> 3, c8 = idx & 7;
        uint32_t soff = (uint32_t)(r * TSTRIDE + c8 * 16);
        size_t g = (size_t)(row0 + r) * Hd + kt * 64 + c8 * 8;
        cpasync16(sb + bufoff + OFF_XH + soff, &g_xhi[g]);
        cpasync16(sb + bufoff + OFF_XL + soff, &g_xlo[g]);
    }
}

__global__ __launch_bounds__(256, 1)
void score_mma(const float* __restrict__ x,
               const float* __restrict__ Va_w,
               const float* __restrict__ Va_b) {
    extern __shared__ char smem[];
    const uint32_t sb = smem_to_u32(smem);
    float* bs_s = (float*)(smem + SM_BS);
    float* va_s = (float*)(smem + SM_VA);
    float* red  = (float*)(smem + SM_RED);

    const int tid = threadIdx.x, lane = tid & 31, wid = tid >> 5;
    const int warp_m = wid & 3, warp_n = wid >> 2;
    const int row0 = blockIdx.x * BM;

    for (int i = tid; i < Hd; i += 256) { bs_s[i] = g_bsum[i]; va_s[i] = Va_w[i]; }
    if (tid < BM) red[tid] = 0.f;

    const uint32_t a_row  = (uint32_t)(lane & 15);
    const uint32_t a_colb = (uint32_t)(((lane >> 4) & 1) * 16);
    const uint32_t b_row  = (uint32_t)((lane & 7) + (lane & 8));
    const uint32_t b_colb = a_colb;

    float rowpart[2][2] = {{0.f, 0.f}, {0.f, 0.f}};
    __syncthreads();

    for (int nb = 0; nb < 4; nb++) {
        float acc[2][8][4];
#pragma unroll
        for (int mi = 0; mi < 2; mi++)
#pragma unroll
            for (int ni = 0; ni < 8; ni++)
#pragma unroll
                for (int q = 0; q < 4; q++) acc[mi][ni][q] = 0.f;

        if (nb >= 1) {  // pipelined path
            load_x_async(smem, SM_BUF0, row0, 0, tid);
            load_w_async(smem, SM_BUF0, nb, 0, tid);
            CP_COMMIT();
        }

        for (int kt = 0; kt < 8; kt++) {
            uint32_t bufoff;
            if (nb == 0) {
                bufoff = SM_BUF0;
                const int kb = kt * 64;
                // convert x fp32 -> bf16 hi/lo: smem + global side-store
#pragma unroll
                for (int it = 0; it < 8; it++) {
                    int idx = tid + it * 256;       // 0..2047 float4s
                    int r = idx >> 4, c4 = idx & 15;
                    size_t gx = (size_t)(row0 + r) * Hd + kb + c4 * 4;
                    float4 v = *(const float4*)&x[gx];
                    __nv_bfloat16 h0 = __float2bfloat16(v.x), h1 = __float2bfloat16(v.y);
                    __nv_bfloat16 h2 = __float2bfloat16(v.z), h3 = __float2bfloat16(v.w);
                    __nv_bfloat16 l0 = __float2bfloat16(v.x - __bfloat162float(h0));
                    __nv_bfloat16 l1 = __float2bfloat16(v.y - __bfloat162float(h1));
                    __nv_bfloat16 l2 = __float2bfloat16(v.z - __bfloat162float(h2));
                    __nv_bfloat16 l3 = __float2bfloat16(v.w - __bfloat162float(h3));
                    uint2 hp, lp;
                    hp.x = (uint32_t)__bfloat16_as_ushort(h0) | ((uint32_t)__bfloat16_as_ushort(h1) << 16);
                    hp.y = (uint32_t)__bfloat16_as_ushort(h2) | ((uint32_t)__bfloat16_as_ushort(h3) << 16);
                    lp.x = (uint32_t)__bfloat16_as_ushort(l0) | ((uint32_t)__bfloat16_as_ushort(l1) << 16);
                    lp.y = (uint32_t)__bfloat16_as_ushort(l2) | ((uint32_t)__bfloat16_as_ushort(l3) << 16);
                    uint32_t off = (uint32_t)(r * TSTRIDE + c4 * 8);
                    *(uint2*)(smem + SM_BUF0 + OFF_XH + off) = hp;
                    *(uint2*)(smem + SM_BUF0 + OFF_XL + off) = lp;
                    *(uint2*)&g_xhi[gx] = hp;
                    *(uint2*)&g_xlo[gx] = lp;
                }
                load_w_async(smem, SM_BUF0, nb, kt, tid);
                CP_COMMIT();
                CP_WAIT(0);
                __syncthreads();
            } else {
                bufoff = (kt & 1) ? SM_BUF1 : SM_BUF0;
                if (kt < 7) {
                    uint32_t nxt = (kt & 1) ? SM_BUF0 : SM_BUF1;
                    load_x_async(smem, nxt, row0, kt + 1, tid);
                    load_w_async(smem, nxt, nb, kt + 1, tid);
                    CP_COMMIT();
                    CP_WAIT(1);
                } else {
                    CP_WAIT(0);
                }
                __syncthreads();
            }

            // ---- MMA on bufoff ----
#pragma unroll
            for (int pass = 0; pass < 3; pass++) {
                const uint32_t xbase = sb + bufoff + (pass == 2 ? OFF_XL : OFF_XH);
                const uint32_t wbase = sb + bufoff + (pass == 1 ? OFF_WL : OFF_WH);
#pragma unroll
                for (int k16 = 0; k16 < 4; k16++) {
                    uint32_t a[2][4];
#pragma unroll
                    for (int mi = 0; mi < 2; mi++) {
                        uint32_t addr = xbase +
                            (uint32_t)(warp_m * 32 + mi * 16 + a_row) * TSTRIDE +
                            (uint32_t)(k16 * 32) + a_colb;
                        ldsm_x4(a[mi][0], a[mi][1], a[mi][2], a[mi][3], addr);
                    }
                    uint32_t b[8][2];
#pragma unroll
                    for (int np = 0; np < 4; np++) {
                        uint32_t r0, r1, r2, r3;
                        uint32_t addr = wbase +
                            (uint32_t)(warp_n * 64 + np * 16 + b_row) * TSTRIDE +
                            (uint32_t)(k16 * 32) + b_colb;
                        ldsm_x4(r0, r1, r2, r3, addr);
                        b[np * 2][0] = r0;     b[np * 2][1] = r2;
                        b[np * 2 + 1][0] = r1; b[np * 2 + 1][1] = r3;
                    }
#pragma unroll
                    for (int mi = 0; mi < 2; mi++)
#pragma unroll
                        for (int ni = 0; ni < 8; ni++)
                            mma16816(acc[mi][ni], a[mi], b[ni]);
                }
            }
            __syncthreads();
        }

        // fused epilogue for this 128-wide N chunk
#pragma unroll
        for (int mi = 0; mi < 2; mi++)
#pragma unroll
            for (int ni = 0; ni < 8; ni++) {
                int n0 = nb * 128 + warp_n * 64 + ni * 8 + (lane & 3) * 2;
                float bs0 = bs_s[n0], bs1 = bs_s[n0 + 1];
                float va0 = va_s[n0], va1 = va_s[n0 + 1];
                rowpart[mi][0] = fmaf(tanhf(acc[mi][ni][0] + bs0), va0, rowpart[mi][0]);
                rowpart[mi][0] = fmaf(tanhf(acc[mi][ni][1] + bs1), va1, rowpart[mi][0]);
                rowpart[mi][1] = fmaf(tanhf(acc[mi][ni][2] + bs0), va0, rowpart[mi][1]);
                rowpart[mi][1] = fmaf(tanhf(acc[mi][ni][3] + bs1), va1, rowpart[mi][1]);
            }
    }

    // reduce across lanes sharing each row, then across warps via smem
#pragma unroll
    for (int mi = 0; mi < 2; mi++)
#pragma unroll
        for (int rh = 0; rh < 2; rh++) {
            float v = rowpart[mi][rh];
            v += __shfl_xor_sync(0xffffffff, v, 1);
            v += __shfl_xor_sync(0xffffffff, v, 2);
            if ((lane & 3) == 0) {
                int row = warp_m * 32 + mi * 16 + rh * 8 + (lane >> 2);
                atomicAdd(&red[row], v);
            }
        }
    __syncthreads();
    if (tid < BM) g_score[row0 + tid] = red[tid] + Va_b[0];
}

// ---------------------------------------------------------------------------
// Kernel 3: softmax over T per batch row.
// ---------------------------------------------------------------------------
__global__ __launch_bounds__(256)
void softmax_kernel(float* __restrict__ out_w) {
    __shared__ float sred[256];
    const int b = blockIdx.x, tid = threadIdx.x;
    const float* s = g_score + (size_t)b * Td;
    float* w = out_w + (size_t)b * Td;

    float m = -1e30f;
    for (int t = tid; t < Td; t += 256) m = fmaxf(m, s[t]);
    sred[tid] = m; __syncthreads();
    for (int o = 128; o > 0; o >>= 1) {
        if (tid < o) sred[tid] = fmaxf(sred[tid], sred[tid + o]);
        __syncthreads();
    }
    m = sred[0]; __syncthreads();

    float sum = 0.f;
    for (int t = tid; t < Td; t += 256) {
        float e = __expf(s[t] - m);
        w[t] = e; sum += e;
    }
    sred[tid] = sum; __syncthreads();
    for (int o = 128; o > 0; o >>= 1) {
        if (tid < o) sred[tid] += sred[tid + o];
        __syncthreads();
    }
    float inv = 1.f / sred[0];
    for (int t = tid; t < Td; t += 256) w[t] *= inv;
}

// ---------------------------------------------------------------------------
// Kernel 4: context[b,h] = sum_t w[b,t] * x[b,t,h]  (MLP=8)
// ---------------------------------------------------------------------------
__global__ __launch_bounds__(256)
void context_kernel(const float* __restrict__ x, const float* __restrict__ w,
                    float* __restrict__ ctx) {
    __shared__ float ws_[Td];
    const int b = blockIdx.y;
    const int h = blockIdx.x * 256 + threadIdx.x;
    for (int t = threadIdx.x; t < Td; t += 256)
        ws_[t] = w[(size_t)b * Td + t];
    __syncthreads();
    const float* xb = x + (size_t)b * Td * Hd + h;
    float a0 = 0.f, a1 = 0.f, a2 = 0.f, a3 = 0.f;
    float a4 = 0.f, a5 = 0.f, a6 = 0.f, a7 = 0.f;
    for (int t = 0; t < Td; t += 8) {
        a0 = fmaf(ws_[t + 0], xb[(size_t)(t + 0) * Hd], a0);
        a1 = fmaf(ws_[t + 1], xb[(size_t)(t + 1) * Hd], a1);
        a2 = fmaf(ws_[t + 2], xb[(size_t)(t + 2) * Hd], a2);
        a3 = fmaf(ws_[t + 3], xb[(size_t)(t + 3) * Hd], a3);
        a4 = fmaf(ws_[t + 4], xb[(size_t)(t + 4) * Hd], a4);
        a5 = fmaf(ws_[t + 5], xb[(size_t)(t + 5) * Hd], a5);
        a6 = fmaf(ws_[t + 6], xb[(size_t)(t + 6) * Hd], a6);
        a7 = fmaf(ws_[t + 7], xb[(size_t)(t + 7) * Hd], a7);
    }
    ctx[(size_t)b * Hd + h] = ((a0 + a1) + (a2 + a3)) + ((a4 + a5) + (a6 + a7));
}

// ---------------------------------------------------------------------------
// Launch
// ---------------------------------------------------------------------------
extern "C" void kernel_launch(void* const* d_in, const int* in_sizes, int n_in,
                              void* d_out, int out_size) {
    const float* x    = (const float*)d_in[0];
    const float* Wa_w = (const float*)d_in[1];
    const float* Wa_b = (const float*)d_in[2];
    const float* Ua_w = (const float*)d_in[3];
    const float* Ua_b = (const float*)d_in[4];
    const float* Va_w = (const float*)d_in[5];
    const float* Va_b = (const float*)d_in[6];

    float* out_ctx = (float*)d_out;             // [B,H]
    float* out_w   = (float*)d_out + Bd * Hd;   // [B,T]

    cudaFuncSetAttribute(score_mma, cudaFuncAttributeMaxDynamicSharedMemorySize,
                         SMEM_TOTAL);

    prep_kernel<<<(Hd * Hd + 255) / 256, 256>>>(Wa_w, Ua_w, Wa_b, Ua_b);
    score_mma<<<Md / BM, 256, SMEM_TOTAL>>>(x, Va_w, Va_b);
    softmax_kernel<<<Bd, 256>>>(out_w);
    context_kernel<<<dim3(Hd / 256, Bd), 256>>>(x, out_w, out_ctx);
}